// round 6
// baseline (speedup 1.0000x reference)
#include <cuda_runtime.h>
#include <cstdint>

// Problem constants (fixed by the reference)
static constexpr int B  = 2048;   // batch
static constexpr int U  = 256;    // units
static constexpr int P  = 256;    // features
static constexpr int G  = 64;     // groups
static constexpr int UT = 16;     // units per CTA (4 per warp, 8 lanes per unit)
static constexpr int SPLIT = 2;   // intra-group batch split (gridDim.z)

#define SOFTPLUS_C 0.5413248546129181f

// Scratch (allocation-free rule: __device__ globals)
__device__ int g_items[B];        // batch indices sorted by group
__device__ int g_start[G + 1];    // group offsets into g_items

__device__ __forceinline__ float softplus_f(float v) {
    // numerically stable: max(v,0) + log1p(exp(-|v|)) (matches jax.nn.softplus f32)
    return fmaxf(v, 0.0f) + log1pf(expf(-fabsf(v)));
}

// Packed f32x2 FMA (Blackwell FFMA2; PTX-only path, ptxas won't auto-fuse)
__device__ __forceinline__ unsigned long long ffma2(unsigned long long a,
                                                    unsigned long long b,
                                                    unsigned long long c) {
    unsigned long long d;
    asm("fma.rn.f32x2 %0, %1, %2, %3;" : "=l"(d) : "l"(a), "l"(b), "l"(c));
    return d;
}
__device__ __forceinline__ float2 unpack_f32x2(unsigned long long v) {
    float2 r;
    asm("mov.b64 {%0, %1}, %2;" : "=f"(r.x), "=f"(r.y) : "l"(v));
    return r;
}

// ---------------------------------------------------------------------------
// Kernel 1: counting-sort batches by group (single block, tiny)
// ---------------------------------------------------------------------------
__global__ void bin_kernel(const int* __restrict__ gid) {
    __shared__ int cnt[G];
    __shared__ int off[G];
    int tid = threadIdx.x;
    if (tid < G) cnt[tid] = 0;
    __syncthreads();
    for (int b = tid; b < B; b += blockDim.x)
        atomicAdd(&cnt[gid[b]], 1);
    __syncthreads();
    if (tid == 0) {
        int s = 0;
        for (int g = 0; g < G; g++) {
            g_start[g] = s;
            off[g] = s;
            s += cnt[g];
        }
        g_start[G] = s;
    }
    __syncthreads();
    for (int b = tid; b < B; b += blockDim.x) {
        int g = gid[b];
        int pos = atomicAdd(&off[g], 1);
        g_items[pos] = b;   // intra-group order nondeterministic; outputs are
                            // per-batch independent -> results deterministic
    }
}

// ---------------------------------------------------------------------------
// Kernel 2: main kernel.
// grid = (U/UT, G, SPLIT), 128 threads (4 warps). Warp owns 4 units; each
// 8-lane subgroup owns one unit row (lane sl handles 16B chunks sl, sl+8,...).
//  - weights (w_mu + fused softplus) in 32KB SMEM, one prologue barrier only
//  - per batch: 8 eps LDG.128 front-batched per lane (4KB in flight/warp),
//    x via __ldg (L1-hot), weights via conflict-free LDS.128
//  - packed fma.rn.f32x2 halves FMA issue count
//  - reduction: 3 shfl_xor within 8-lane groups (covers 4 units at once)
// ---------------------------------------------------------------------------
__global__ __launch_bounds__(128, 7) void multilevel_dense_kernel(
    const float* __restrict__ x,
    const float* __restrict__ w_mu,
    const float* __restrict__ w_sigma,
    const float* __restrict__ b_mu,
    const float* __restrict__ b_sigma,
    const float* __restrict__ eps_w,
    const float* __restrict__ eps_b,
    float* __restrict__ out)
{
    __shared__ __align__(16) float s_wmu[UT * P];   // 16 KB
    __shared__ __align__(16) float s_sp [UT * P];   // 16 KB

    const int g    = blockIdx.y;
    const int u0   = blockIdx.x * UT;
    const int z    = blockIdx.z;
    const int tid  = threadIdx.x;
    const int warp = tid >> 5;
    const int lane = tid & 31;
    const int sub  = lane >> 3;       // which of the warp's 4 units
    const int sl   = lane & 7;        // lane within the 8-lane subgroup
    const int lu   = warp * 4 + sub;  // CTA-local unit (0..15)
    const int u    = u0 + lu;         // global unit

    // ---- weight slab load with FUSED softplus (one barrier, then free-run)
    {
        const float4* wm4 = reinterpret_cast<const float4*>(w_mu    + ((size_t)g * U + u0) * P);
        const float4* ws4 = reinterpret_cast<const float4*>(w_sigma + ((size_t)g * U + u0) * P);
        float4* swm = reinterpret_cast<float4*>(s_wmu);
        float4* ssp = reinterpret_cast<float4*>(s_sp);
        #pragma unroll
        for (int i = tid; i < UT * P / 4; i += 128) {
            swm[i] = wm4[i];
            float4 v = ws4[i];
            float4 r;
            r.x = softplus_f(SOFTPLUS_C + v.x);
            r.y = softplus_f(SOFTPLUS_C + v.y);
            r.z = softplus_f(SOFTPLUS_C + v.z);
            r.w = softplus_f(SOFTPLUS_C + v.w);
            ssp[i] = r;
        }
    }

    // per-unit bias constants (all 8 lanes of a subgroup compute the same)
    const float bmu = b_mu[g * U + u];
    const float spb = softplus_f(SOFTPLUS_C + b_sigma[g * U + u]);

    __syncthreads();   // slabs visible; last barrier in the kernel

    const int start = g_start[g];
    const int end   = g_start[g + 1];

    // smem weight base for this lane's unit, as 16B packed-pair chunks
    const ulonglong2* sw2 = reinterpret_cast<const ulonglong2*>(s_wmu) + lu * (P / 4);
    const ulonglong2* ss2 = reinterpret_cast<const ulonglong2*>(s_sp)  + lu * (P / 4);

    for (int idx = start + z; idx < end; idx += SPLIT) {
        const int b = g_items[idx];
        const ulonglong2* e2 = reinterpret_cast<const ulonglong2*>(eps_w + ((size_t)b * U + u) * P);
        const ulonglong2* x2 = reinterpret_cast<const ulonglong2*>(x + (size_t)b * P);

        // front-batch all 8 eps LDG.128 (4KB in flight per warp)
        ulonglong2 e[8];
        #pragma unroll
        for (int j = 0; j < 8; j++)
            e[j] = __ldcs(e2 + sl + 8 * j);

        unsigned long long acc01 = 0ull, acc23 = 0ull;   // bits of (0.f,0.f)
        #pragma unroll
        for (int j = 0; j < 8; j++) {
            ulonglong2 xv = __ldg(x2 + sl + 8 * j);      // L1/L2-hot
            ulonglong2 w  = sw2[sl + 8 * j];
            ulonglong2 s  = ss2[sl + 8 * j];
            acc01 = ffma2(ffma2(s.x, e[j].x, w.x), xv.x, acc01);
            acc23 = ffma2(ffma2(s.y, e[j].y, w.y), xv.y, acc23);
        }

        float2 a = unpack_f32x2(acc01);
        float2 c = unpack_f32x2(acc23);
        float r = (a.x + a.y) + (c.x + c.y);

        // 8-lane subgroup reduction (3 steps, covers 4 units per warp at once)
        r += __shfl_xor_sync(0xffffffffu, r, 1);
        r += __shfl_xor_sync(0xffffffffu, r, 2);
        r += __shfl_xor_sync(0xffffffffu, r, 4);

        if (sl == 0)
            out[(size_t)b * U + u] = r + bmu + spb * eps_b[(size_t)b * U + u];
    }
}

// ---------------------------------------------------------------------------
// Launch
// Input order (metadata): x, gid, w_mu, w_sigma, b_mu, b_sigma, eps_w, eps_b
// ---------------------------------------------------------------------------
extern "C" void kernel_launch(void* const* d_in, const int* in_sizes, int n_in,
                              void* d_out, int out_size) {
    const float* x       = (const float*)d_in[0];
    const int*   gid     = (const int*)  d_in[1];
    const float* w_mu    = (const float*)d_in[2];
    const float* w_sigma = (const float*)d_in[3];
    const float* b_mu    = (const float*)d_in[4];
    const float* b_sigma = (const float*)d_in[5];
    const float* eps_w   = (const float*)d_in[6];
    const float* eps_b   = (const float*)d_in[7];
    float* out = (float*)d_out;

    // 1) bin batches by group
    bin_kernel<<<1, 256>>>(gid);

    // 2) main kernel
    dim3 grid(U / UT, G, SPLIT);   // (16, 64, 2) = 2048 CTAs
    multilevel_dense_kernel<<<grid, 128>>>(x, w_mu, w_sigma, b_mu, b_sigma,
                                           eps_w, eps_b, out);
}

// round 7
// speedup vs baseline: 1.2689x; 1.2689x over previous
#include <cuda_runtime.h>
#include <cstdint>

// Problem constants (fixed by the reference)
static constexpr int B  = 2048;   // batch
static constexpr int U  = 256;    // units
static constexpr int P  = 256;    // features
static constexpr int G  = 64;     // groups
static constexpr int UT = 8;      // units per CTA (1 per warp)
static constexpr int SPLIT = 2;   // intra-group batch split (gridDim.z)

static constexpr int STAGES = 5;  // per-warp ring stages (1KB each)
static constexpr int DEPTH  = 3;  // cp.async groups in flight

#define SOFTPLUS_C 0.5413248546129181f

// Scratch (allocation-free rule: __device__ globals)
__device__ int g_items[B];        // batch indices sorted by group
__device__ int g_start[G + 1];    // group offsets into g_items

__device__ __forceinline__ float softplus_f(float v) {
    // numerically stable: max(v,0) + log1p(exp(-|v|)) (matches jax.nn.softplus f32)
    return fmaxf(v, 0.0f) + log1pf(expf(-fabsf(v)));
}

// warp sum: 5-step butterfly (sm_103 has NO redux.f32)
__device__ __forceinline__ float warp_sum(float v) {
    #pragma unroll
    for (int o = 16; o; o >>= 1) v += __shfl_xor_sync(0xffffffffu, v, o);
    return v;
}

// ---- cp.async helpers (.cg = L2-only, right for streaming eps) ----
__device__ __forceinline__ void cp_async16(uint32_t dst_smem, const void* src) {
    asm volatile("cp.async.cg.shared.global [%0], [%1], 16;\n"
                 :: "r"(dst_smem), "l"(src) : "memory");
}
__device__ __forceinline__ void cp_commit() {
    asm volatile("cp.async.commit_group;\n" ::: "memory");
}
template <int N>
__device__ __forceinline__ void cp_wait() {
    asm volatile("cp.async.wait_group %0;\n" :: "n"(N) : "memory");
}

// ---------------------------------------------------------------------------
// Kernel 1: counting-sort batches by group (single block, tiny)
// ---------------------------------------------------------------------------
__global__ void bin_kernel(const int* __restrict__ gid) {
    __shared__ int cnt[G];
    __shared__ int off[G];
    int tid = threadIdx.x;
    if (tid < G) cnt[tid] = 0;
    __syncthreads();
    for (int b = tid; b < B; b += blockDim.x)
        atomicAdd(&cnt[gid[b]], 1);
    __syncthreads();
    if (tid == 0) {
        int s = 0;
        for (int g = 0; g < G; g++) {
            g_start[g] = s;
            off[g] = s;
            s += cnt[g];
        }
        g_start[G] = s;
    }
    __syncthreads();
    for (int b = tid; b < B; b += blockDim.x) {
        int g = gid[b];
        int pos = atomicAdd(&off[g], 1);
        g_items[pos] = b;   // intra-group order nondeterministic; outputs are
                            // per-batch independent -> results deterministic
    }
}

// ---------------------------------------------------------------------------
// Kernel 2: main kernel — zero barriers, register-resident weights,
// per-warp PRIVATE cp.async ring (5 stages x 1KB, depth 3 in flight).
// grid = (U/UT, G, SPLIT), 256 threads. Warp w owns unit u = bx*8 + w of
// group g and free-runs: eps DRAM latency is hidden by the 3-deep ring,
// x/L2 latency by issuing x loads before the cp wait, the shuffle tail by
// the already-in-flight next stages. No __syncthreads anywhere.
// ---------------------------------------------------------------------------
__global__ __launch_bounds__(256) void multilevel_dense_kernel(
    const float* __restrict__ x,
    const float* __restrict__ w_mu,
    const float* __restrict__ w_sigma,
    const float* __restrict__ b_mu,
    const float* __restrict__ b_sigma,
    const float* __restrict__ eps_w,
    const float* __restrict__ eps_b,
    float* __restrict__ out)
{
    // per-warp private ring: [warp][stage][64 float4 slots] = 8*5*1KB = 40KB
    __shared__ __align__(16) float4 ring[UT][STAGES][P / 4];

    const int g    = blockIdx.y;
    const int z    = blockIdx.z;
    const int warp = threadIdx.x >> 5;
    const int lane = threadIdx.x & 31;
    const int u    = blockIdx.x * UT + warp;

    // ---- persistent per-lane weights: features [lane*4..+4) and [128+lane*4..+4)
    float4 wA, wB, sA, sB;
    {
        const float4* wm4 = reinterpret_cast<const float4*>(w_mu    + ((size_t)g * U + u) * P);
        const float4* ws4 = reinterpret_cast<const float4*>(w_sigma + ((size_t)g * U + u) * P);
        wA = wm4[lane];
        wB = wm4[lane + 32];
        float4 vA = ws4[lane];
        float4 vB = ws4[lane + 32];
        sA.x = softplus_f(SOFTPLUS_C + vA.x);
        sA.y = softplus_f(SOFTPLUS_C + vA.y);
        sA.z = softplus_f(SOFTPLUS_C + vA.z);
        sA.w = softplus_f(SOFTPLUS_C + vA.w);
        sB.x = softplus_f(SOFTPLUS_C + vB.x);
        sB.y = softplus_f(SOFTPLUS_C + vB.y);
        sB.z = softplus_f(SOFTPLUS_C + vB.z);
        sB.w = softplus_f(SOFTPLUS_C + vB.w);
    }
    const float bmu = b_mu[g * U + u];
    const float spb = softplus_f(SOFTPLUS_C + b_sigma[g * U + u]);

    const int base = g_start[g] + z;
    const int end  = g_start[g + 1];
    const int nb   = (end > base) ? (end - base + SPLIT - 1) / SPLIT : 0;

    const uint32_t ring_sh =
        (uint32_t)__cvta_generic_to_shared(&ring[warp][0][0]);

    // ---- prologue: fill DEPTH stages (one commit per stage, possibly empty)
    #pragma unroll
    for (int s = 0; s < DEPTH; s++) {
        if (s < nb) {
            const int b = g_items[base + s * SPLIT];
            const float4* e = reinterpret_cast<const float4*>(eps_w + ((size_t)b * U + u) * P);
            const uint32_t dst = ring_sh + (uint32_t)s * (P / 4) * 16;
            cp_async16(dst + lane * 16,        e + lane);
            cp_async16(dst + (lane + 32) * 16, e + lane + 32);
        }
        cp_commit();
    }

    if (nb == 0) return;

    int stage  = 0;
    int b_cur  = g_items[base];

    for (int j = 0; j < nb; j++) {
        // prefetch next batch index (hides g_items L2 latency)
        const int b_nxt = (j + 1 < nb) ? g_items[base + (j + 1) * SPLIT] : 0;

        // issue cp.async for batch j+DEPTH into stage (stage+DEPTH)%STAGES
        {
            int ws = stage + DEPTH;
            if (ws >= STAGES) ws -= STAGES;
            if (j + DEPTH < nb) {
                const int bf = g_items[base + (j + DEPTH) * SPLIT];
                const float4* e = reinterpret_cast<const float4*>(eps_w + ((size_t)bf * U + u) * P);
                const uint32_t dst = ring_sh + (uint32_t)ws * (P / 4) * 16;
                cp_async16(dst + lane * 16,        e + lane);
                cp_async16(dst + (lane + 32) * 16, e + lane + 32);
            }
            cp_commit();
        }

        // x / eps_b loads for the CURRENT batch, issued before the wait
        const float4* xb = reinterpret_cast<const float4*>(x + (size_t)b_cur * P);
        float4 xa  = __ldg(&xb[lane]);
        float4 xbv = __ldg(&xb[lane + 32]);
        float  eb  = __ldg(&eps_b[(size_t)b_cur * U + u]);

        cp_wait<DEPTH>();   // oldest pending group (batch j's stage) complete

        const float4 ea  = ring[warp][stage][lane];
        const float4 eb4 = ring[warp][stage][lane + 32];

        float acc = 0.0f;
        acc = fmaf(fmaf(sA.x, ea.x,  wA.x), xa.x,  acc);
        acc = fmaf(fmaf(sA.y, ea.y,  wA.y), xa.y,  acc);
        acc = fmaf(fmaf(sA.z, ea.z,  wA.z), xa.z,  acc);
        acc = fmaf(fmaf(sA.w, ea.w,  wA.w), xa.w,  acc);
        acc = fmaf(fmaf(sB.x, eb4.x, wB.x), xbv.x, acc);
        acc = fmaf(fmaf(sB.y, eb4.y, wB.y), xbv.y, acc);
        acc = fmaf(fmaf(sB.z, eb4.z, wB.z), xbv.z, acc);
        acc = fmaf(fmaf(sB.w, eb4.w, wB.w), xbv.w, acc);

        acc = warp_sum(acc);   // 3 more stages already in flight during this tail

        if (lane == 0)
            out[(size_t)b_cur * U + u] = acc + bmu + spb * eb;

        b_cur = b_nxt;
        if (++stage == STAGES) stage = 0;
    }
}

// ---------------------------------------------------------------------------
// Launch
// Input order (metadata): x, gid, w_mu, w_sigma, b_mu, b_sigma, eps_w, eps_b
// ---------------------------------------------------------------------------
extern "C" void kernel_launch(void* const* d_in, const int* in_sizes, int n_in,
                              void* d_out, int out_size) {
    const float* x       = (const float*)d_in[0];
    const int*   gid     = (const int*)  d_in[1];
    const float* w_mu    = (const float*)d_in[2];
    const float* w_sigma = (const float*)d_in[3];
    const float* b_mu    = (const float*)d_in[4];
    const float* b_sigma = (const float*)d_in[5];
    const float* eps_w   = (const float*)d_in[6];
    const float* eps_b   = (const float*)d_in[7];
    float* out = (float*)d_out;

    // 1) bin batches by group
    bin_kernel<<<1, 256>>>(gid);

    // 2) main kernel (no barriers; weights in regs; per-warp cp.async ring)
    dim3 grid(U / UT, G, SPLIT);   // (32, 64, 2) = 4096 CTAs
    multilevel_dense_kernel<<<grid, 256>>>(x, w_mu, w_sigma, b_mu, b_sigma,
                                           eps_w, eps_b, out);
}